// round 9
// baseline (speedup 1.0000x reference)
#include <cuda_runtime.h>
#include <math.h>
#include <stdint.h>

// MoE router: tf32 mma.sync (3-term split) + exact fp64 recheck for near-ties.
// x: [16384, 2048] f32, W: [2048, 64] f32
// out (f32): dispatch[16384*64], probs[16384*64], tkp[16384*2], tki[16384*2]

#define M_TOK   16384
#define K_DIM   2048
#define N_EXP   64
#define BM      128
#define BK      32
#define NT      (K_DIM / BK)          // 64
#define THREADS 256
#define GAP_TH  2e-3f

// stride 36 -> bank = (4g+i) mod 32: conflict-free frag loads.
#define XH_OFF       0                // 128 x 36
#define XL_OFF       4608
#define WH_OFF       9216             // 64 x 36 (W^T: [n][k])
#define WL_OFF       11520
#define STAGE_FLOATS 13824
#define SMEM_BYTES   (2 * STAGE_FLOATS * 4)   // 110592 B

#define OFF_DISP  0
#define OFF_PROBS (M_TOK * N_EXP)
#define OFF_TKP   (2 * M_TOK * N_EXP)
#define OFF_TKI   (2 * M_TOK * N_EXP + 2 * M_TOK)

__device__ __forceinline__ unsigned f2tf32(float f) {
    unsigned u;
    asm("cvt.rna.tf32.f32 %0, %1;" : "=r"(u) : "f"(f));
    return u;
}

__device__ __forceinline__ void mma_tf32(float* c, const unsigned* a, const unsigned* b) {
    asm volatile(
        "mma.sync.aligned.m16n8k8.row.col.f32.tf32.tf32.f32 "
        "{%0,%1,%2,%3}, {%4,%5,%6,%7}, {%8,%9}, {%0,%1,%2,%3};"
        : "+f"(c[0]), "+f"(c[1]), "+f"(c[2]), "+f"(c[3])
        : "r"(a[0]), "r"(a[1]), "r"(a[2]), "r"(a[3]), "r"(b[0]), "r"(b[1]));
}

__global__ __launch_bounds__(THREADS, 1)
void moe_mma_kernel(const float* __restrict__ x,
                    const float* __restrict__ W,
                    float* __restrict__ out) {
    extern __shared__ float sm[];
    __shared__ float s_max[BM], s_inv[BM];
    __shared__ int   s_i1[BM], s_i2[BM], s_i3[BM];
    __shared__ int   s_nflag;
    __shared__ int   s_flist[BM];

    const int t    = threadIdx.x;
    const int wid  = t >> 5;
    const int lane = t & 31;
    const int g    = lane >> 2;
    const int qi   = lane & 3;
    const int tok0 = blockIdx.x * BM;
    const int m0   = wid * 16;

    const int xrow  = t >> 1;
    const int xhalf = t & 1;
    const float* xg = x + (size_t)(tok0 + xrow) * K_DIM + xhalf * 16;
    const int wn  = t & 63;
    const int wkq = t >> 6;
    const float* wg = W + (size_t)(wkq * 8) * N_EXP + wn;

    if (t == 0) s_nflag = 0;

    float4 xb[4];
    float  wb[8];
#pragma unroll
    for (int j = 0; j < 4; j++) xb[j] = *reinterpret_cast<const float4*>(xg + j * 4);
#pragma unroll
    for (int j = 0; j < 8; j++) wb[j] = wg[(size_t)j * N_EXP];

    float acc[8][4];
#pragma unroll
    for (int n = 0; n < 8; n++)
#pragma unroll
        for (int c = 0; c < 4; c++) acc[n][c] = 0.f;

#pragma unroll 1
    for (int kt = 0; kt < NT; kt++) {
        const int s = kt & 1;
        unsigned* sth = reinterpret_cast<unsigned*>(sm + s * STAGE_FLOATS);

        // convert prefetched tile -> tf32 hi/lo, store
#pragma unroll
        for (int j = 0; j < 4; j++) {
            float4 v = xb[j];
            uint4 h, l;
            h.x = f2tf32(v.x); h.y = f2tf32(v.y); h.z = f2tf32(v.z); h.w = f2tf32(v.w);
            l.x = f2tf32(v.x - __uint_as_float(h.x));
            l.y = f2tf32(v.y - __uint_as_float(h.y));
            l.z = f2tf32(v.z - __uint_as_float(h.z));
            l.w = f2tf32(v.w - __uint_as_float(h.w));
            int o = xrow * 36 + xhalf * 16 + j * 4;
            *reinterpret_cast<uint4*>(sth + XH_OFF + o) = h;
            *reinterpret_cast<uint4*>(sth + XL_OFF + o) = l;
        }
#pragma unroll
        for (int j = 0; j < 8; j++) {
            unsigned h = f2tf32(wb[j]);
            unsigned l = f2tf32(wb[j] - __uint_as_float(h));
            int o = wn * 36 + wkq * 8 + j;
            sth[WH_OFF + o] = h;
            sth[WL_OFF + o] = l;
        }
        __syncthreads();

        // prefetch next tile
        if (kt + 1 < NT) {
            const float* xgn = xg + (kt + 1) * BK;
#pragma unroll
            for (int j = 0; j < 4; j++) xb[j] = *reinterpret_cast<const float4*>(xgn + j * 4);
            const float* wgn = wg + (size_t)(kt + 1) * BK * N_EXP;
#pragma unroll
            for (int j = 0; j < 8; j++) wb[j] = wgn[(size_t)j * N_EXP];
        }

        // compute: 4 k8 x 8 nt x 3 terms
        const unsigned* xh = sth + XH_OFF;
        const unsigned* xl = sth + XL_OFF;
        const unsigned* wh = sth + WH_OFF;
        const unsigned* wl = sth + WL_OFF;
        const int offa = (m0 + g) * 36 + qi;
        const int offb0 = g * 36 + qi;
#pragma unroll
        for (int ks = 0; ks < 4; ks++) {
            const int oa = offa + ks * 8;
            unsigned ah[4], al[4];
            ah[0] = xh[oa];     ah[1] = xh[oa + 8 * 36];
            ah[2] = xh[oa + 4]; ah[3] = xh[oa + 8 * 36 + 4];
            al[0] = xl[oa];     al[1] = xl[oa + 8 * 36];
            al[2] = xl[oa + 4]; al[3] = xl[oa + 8 * 36 + 4];
#pragma unroll
            for (int nt = 0; nt < 8; nt++) {
                const int ob = offb0 + nt * 8 * 36 + ks * 8;
                unsigned bh[2] = { wh[ob], wh[ob + 4] };
                unsigned bl[2] = { wl[ob], wl[ob + 4] };
                mma_tf32(acc[nt], ah, bh);
                mma_tf32(acc[nt], al, bh);
                mma_tf32(acc[nt], ah, bl);
            }
        }
    }
    __syncthreads();

    // dump logits to smem [128][65]
    float* lg = sm;
#pragma unroll
    for (int nt = 0; nt < 8; nt++) {
        int c0 = nt * 8 + qi * 2;
        lg[(m0 + g) * 65 + c0]         = acc[nt][0];
        lg[(m0 + g) * 65 + c0 + 1]     = acc[nt][1];
        lg[(m0 + g + 8) * 65 + c0]     = acc[nt][2];
        lg[(m0 + g + 8) * 65 + c0 + 1] = acc[nt][3];
    }
    __syncthreads();

    // phase 1: per-token top-3 + softmax denom; flag near-ties
    if (t < BM) {
        const float* row = lg + t * 65;
        float b1 = -INFINITY, b2 = -INFINITY, b3 = -INFINITY;
        int i1 = 0, i2 = 0, i3 = 0;
#pragma unroll
        for (int e = 0; e < N_EXP; e++) {
            float v = row[e];
            if (v > b1)      { b3 = b2; i3 = i2; b2 = b1; i2 = i1; b1 = v; i1 = e; }
            else if (v > b2) { b3 = b2; i3 = i2; b2 = v;  i2 = e; }
            else if (v > b3) { b3 = v;  i3 = e; }
        }
        float ssum = 0.f;
#pragma unroll
        for (int e = 0; e < N_EXP; e++) ssum += __expf(row[e] - b1);
        s_max[t] = b1;
        s_inv[t] = 1.f / ssum;
        s_i1[t] = i1; s_i2[t] = i2; s_i3[t] = i3;
        if ((b1 - b2 < GAP_TH) || (b2 - b3 < GAP_TH)) {
            int slot = atomicAdd(&s_nflag, 1);
            s_flist[slot] = t;
        }
    }
    __syncthreads();

    // recheck: one warp per flagged token, exact fp64 logits for top-3
    const int nflag = s_nflag;
    for (int f = wid; f < nflag; f += 8) {
        const int tok = s_flist[f];
        const int e0 = s_i1[tok], e1 = s_i2[tok], e2 = s_i3[tok];
        const float* xr = x + (size_t)(tok0 + tok) * K_DIM;
        double d0 = 0.0, d1 = 0.0, d2 = 0.0;
        for (int k = lane; k < K_DIM; k += 32) {
            double xv = (double)xr[k];
            const float* wrow = W + (size_t)k * N_EXP;
            d0 = fma(xv, (double)wrow[e0], d0);
            d1 = fma(xv, (double)wrow[e1], d1);
            d2 = fma(xv, (double)wrow[e2], d2);
        }
#pragma unroll
        for (int off = 16; off > 0; off >>= 1) {
            d0 += __shfl_xor_sync(0xffffffff, d0, off);
            d1 += __shfl_xor_sync(0xffffffff, d1, off);
            d2 += __shfl_xor_sync(0xffffffff, d2, off);
        }
        if (lane == 0) {
            double v[3] = { d0, d1, d2 };
            int    ix[3] = { e0, e1, e2 };
            // sort 3 descending, tie -> lower index
#pragma unroll
            for (int a = 0; a < 2; a++)
#pragma unroll
                for (int b = 0; b < 2 - a; b++) {
                    bool sw = (v[b] < v[b + 1]) ||
                              (v[b] == v[b + 1] && ix[b] > ix[b + 1]);
                    if (sw) {
                        double tv = v[b]; v[b] = v[b + 1]; v[b + 1] = tv;
                        int ti = ix[b]; ix[b] = ix[b + 1]; ix[b + 1] = ti;
                    }
                }
            s_i1[tok] = ix[0];
            s_i2[tok] = ix[1];
        }
    }
    __syncthreads();

    // phase 1b: tkp/tki from (possibly corrected) indices
    if (t < BM) {
        const float* row = lg + t * 65;
        int i1 = s_i1[t], i2 = s_i2[t];
        float b1 = s_max[t], inv = s_inv[t];
        int gtok = tok0 + t;
        out[OFF_TKP + gtok * 2 + 0] = __expf(row[i1] - b1) * inv;
        out[OFF_TKP + gtok * 2 + 1] = __expf(row[i2] - b1) * inv;
        out[OFF_TKI + gtok * 2 + 0] = (float)i1;
        out[OFF_TKI + gtok * 2 + 1] = (float)i2;
    }
    __syncthreads();

    // phase 2: coalesced probs + dispatch
#pragma unroll
    for (int idx = t; idx < BM * N_EXP; idx += THREADS) {
        int tok = idx >> 6;
        int e   = idx & 63;
        float p = __expf(lg[tok * 65 + e] - s_max[tok]) * s_inv[tok];
        int gtok = tok0 + tok;
        out[OFF_PROBS + (size_t)gtok * N_EXP + e] = p;
        out[OFF_DISP  + (size_t)gtok * N_EXP + e] =
            (e == s_i1[tok] || e == s_i2[tok]) ? 1.f : 0.f;
    }
}

extern "C" void kernel_launch(void* const* d_in, const int* in_sizes, int n_in,
                              void* d_out, int out_size) {
    const float* x = (const float*)d_in[0];
    const float* W = (const float*)d_in[1];
    float* out = (float*)d_out;

    static bool attr_set = false;
    if (!attr_set) {
        cudaFuncSetAttribute(moe_mma_kernel,
                             cudaFuncAttributeMaxDynamicSharedMemorySize, SMEM_BYTES);
        attr_set = true;
    }
    moe_mma_kernel<<<M_TOK / BM, THREADS, SMEM_BYTES>>>(x, W, out);
}